// round 1
// baseline (speedup 1.0000x reference)
#include <cuda_runtime.h>
#include <cstddef>

#define HID    1024
#define EMBED  512
#define BATCH  64
#define MAXLEN 1024
#define VOCAB  50257

// ---------------- scratch (no allocations allowed) ----------------
__device__ float g_dproj[BATCH * HID];            // dec @ w1_d
__device__ float g_epart[16 * MAXLEN * BATCH];    // attention partials per n-chunk
__device__ float g_alpha[MAXLEN * BATCH];         // softmax weights  [t][b]
__device__ float g_cpart[8 * BATCH * HID];        // context partials per t-segment
__device__ float g_x[BATCH * (EMBED + HID)];      // concat(emb, c)
__device__ float g_gi[BATCH * 3 * HID];
__device__ float g_gh[BATCH * 3 * HID];
__device__ float g_h0[BATCH * HID];

// ---------------- generic M=64 GEMM: C[64xN] = A[64xK] @ B (+bias) ----------------
// BT=true : B is [N][K] row-major (i.e. C = A @ B^T)  — weight matrices
// BT=false: B is [K][N] row-major (ld == N)           — dproj
template <bool BT>
__global__ void gemm64(const float* __restrict__ A, const float* __restrict__ B,
                       const float* __restrict__ bias, float* __restrict__ C,
                       int N, int K, int ldc) {
    __shared__ float As[64][16];
    __shared__ float Bs[16][64];
    const int nT  = blockIdx.x * 64;
    const int tid = threadIdx.x;           // 256 threads
    const int tx  = tid & 15, ty = tid >> 4;
    const int m4  = tid >> 2, kq = tid & 3;

    float acc[4][4] = {};
    for (int k0 = 0; k0 < K; k0 += 16) {
        // A tile: one float4 per thread, coalesced
        float4 av = *(const float4*)(A + (size_t)m4 * K + k0 + kq * 4);
        *(float4*)&As[m4][kq * 4] = av;
        if (BT) {
            int n = tid >> 2;
            int gn = nT + n;
            float4 bv = make_float4(0.f, 0.f, 0.f, 0.f);
            if (gn < N) bv = *(const float4*)(B + (size_t)gn * K + k0 + kq * 4);
            Bs[kq * 4 + 0][n] = bv.x;
            Bs[kq * 4 + 1][n] = bv.y;
            Bs[kq * 4 + 2][n] = bv.z;
            Bs[kq * 4 + 3][n] = bv.w;
        } else {
            #pragma unroll
            for (int e2 = 0; e2 < 4; e2++) {
                int lin = tid + e2 * 256;
                int kk = lin >> 6, n = lin & 63;
                int gn = nT + n;
                Bs[kk][n] = (gn < N) ? B[(size_t)(k0 + kk) * N + gn] : 0.f;
            }
        }
        __syncthreads();
        #pragma unroll
        for (int kk = 0; kk < 16; kk++) {
            float4 b4 = *(const float4*)&Bs[kk][tx * 4];
            float bj[4] = {b4.x, b4.y, b4.z, b4.w};
            #pragma unroll
            for (int i = 0; i < 4; i++) {
                float a = As[ty * 4 + i][kk];
                #pragma unroll
                for (int j = 0; j < 4; j++) acc[i][j] = fmaf(a, bj[j], acc[i][j]);
            }
        }
        __syncthreads();
    }
    #pragma unroll
    for (int i = 0; i < 4; i++) {
        int m = ty * 4 + i;
        #pragma unroll
        for (int j = 0; j < 4; j++) {
            int n = nT + tx * 4 + j;
            if (n < N) {
                float v = acc[i][j];
                if (bias) v += bias[n];
                C[(size_t)m * ldc + n] = v;
            }
        }
    }
}

// ---------------- fused attention energy: e[t][b] = tanh(E@W1e + dproj) @ w2 ----------------
// grid = (16 n-chunks  [x, fastest -> co-resident blocks share the A tile],
//         1024 t-tiles [y])
__global__ void attn_kernel(const float* __restrict__ E,
                            const float* __restrict__ w1e,
                            const float* __restrict__ w2) {
    __shared__ float As[64][16];
    __shared__ float Bs[16][64];
    const int nc = blockIdx.x;
    const int t  = blockIdx.y;
    const float* A = E + (size_t)t * 64 * HID;   // rows = 64 batch entries of timestep t
    const int tid = threadIdx.x;
    const int tx = tid & 15, ty = tid >> 4;
    const int m4 = tid >> 2, kq = tid & 3;

    float acc[4][4] = {};
    for (int k0 = 0; k0 < HID; k0 += 16) {
        float4 av = *(const float4*)(A + (size_t)m4 * HID + k0 + kq * 4);
        *(float4*)&As[m4][kq * 4] = av;
        #pragma unroll
        for (int e2 = 0; e2 < 4; e2++) {
            int lin = tid + e2 * 256;
            int kk = lin >> 6, n = lin & 63;
            Bs[kk][n] = w1e[(size_t)(k0 + kk) * HID + nc * 64 + n];
        }
        __syncthreads();
        #pragma unroll
        for (int kk = 0; kk < 16; kk++) {
            float4 b4 = *(const float4*)&Bs[kk][tx * 4];
            float bj[4] = {b4.x, b4.y, b4.z, b4.w};
            #pragma unroll
            for (int i = 0; i < 4; i++) {
                float a = As[ty * 4 + i][kk];
                #pragma unroll
                for (int j = 0; j < 4; j++) acc[i][j] = fmaf(a, bj[j], acc[i][j]);
            }
        }
        __syncthreads();
    }
    // tanh + weighted reduce over the 64 attention dims this block owns
    float rowsum[4];
    #pragma unroll
    for (int i = 0; i < 4; i++) {
        int b = ty * 4 + i;
        float s = 0.f;
        #pragma unroll
        for (int j = 0; j < 4; j++) {
            int n = nc * 64 + tx * 4 + j;
            float pre = acc[i][j] + g_dproj[b * HID + n];
            s += tanhf(pre) * w2[n];
        }
        #pragma unroll
        for (int off = 8; off; off >>= 1)
            s += __shfl_down_sync(0xffffffffu, s, off, 16);
        rowsum[i] = s;
    }
    if (tx == 0) {
        #pragma unroll
        for (int i = 0; i < 4; i++)
            g_epart[nc * (MAXLEN * BATCH) + t * 64 + ty * 4 + i] = rowsum[i];
    }
}

// ---------------- softmax over t (reduces the 16 partials first) ----------------
__global__ void softmax_kernel() {
    const int b = blockIdx.x;
    __shared__ float es[MAXLEN];
    __shared__ float red[256];
    const int tid = threadIdx.x;

    float mx = -1e30f;
    for (int t = tid; t < MAXLEN; t += 256) {
        float s = 0.f;
        #pragma unroll
        for (int p = 0; p < 16; p++) s += g_epart[p * (MAXLEN * BATCH) + t * 64 + b];
        es[t] = s;
        mx = fmaxf(mx, s);
    }
    red[tid] = mx; __syncthreads();
    for (int s2 = 128; s2; s2 >>= 1) {
        if (tid < s2) red[tid] = fmaxf(red[tid], red[tid + s2]);
        __syncthreads();
    }
    mx = red[0]; __syncthreads();

    float sum = 0.f;
    for (int t = tid; t < MAXLEN; t += 256) {
        float v = __expf(es[t] - mx);
        es[t] = v;
        sum += v;
    }
    red[tid] = sum; __syncthreads();
    for (int s2 = 128; s2; s2 >>= 1) {
        if (tid < s2) red[tid] += red[tid + s2];
        __syncthreads();
    }
    float inv = 1.f / red[0];
    for (int t = tid; t < MAXLEN; t += 256) g_alpha[t * 64 + b] = es[t] * inv;
}

// ---------------- context: c[b] = sum_t alpha[t][b] * E[t][b] (t split 8 ways) ----------------
__global__ void context_kernel(const float* __restrict__ E) {
    const int b = blockIdx.x, seg = blockIdx.y;
    const int h = threadIdx.x;   // 1024
    float acc = 0.f;
    #pragma unroll 4
    for (int t = seg * 128; t < (seg + 1) * 128; t++)
        acc = fmaf(g_alpha[t * 64 + b], E[((size_t)t * 64 + b) * HID + h], acc);
    g_cpart[(seg * BATCH + b) * HID + h] = acc;
}

// ---------------- x = concat(embedding[cur], c) ----------------
__global__ void build_x(const int* __restrict__ cur, const float* __restrict__ emb) {
    const int b = blockIdx.x, tid = threadIdx.x;  // 512 threads
    const int tok = cur[b];
    for (int k = tid; k < EMBED; k += 512)
        g_x[b * (EMBED + HID) + k] = emb[(size_t)tok * EMBED + k];
    for (int k = tid; k < HID; k += 512) {
        float s = 0.f;
        #pragma unroll
        for (int p = 0; p < 8; p++) s += g_cpart[(p * BATCH + b) * HID + k];
        g_x[b * (EMBED + HID) + EMBED + k] = s;
    }
}

// ---------------- GRU gates ----------------
__global__ void gru_gates(const float* __restrict__ hprev,
                          float* __restrict__ out1, float* __restrict__ out2) {
    const int idx = blockIdx.x * 256 + threadIdx.x;  // 64*1024 total
    const int b = idx >> 10, q = idx & 1023;
    const float* gi = g_gi + b * 3072;
    const float* gh = g_gh + b * 3072;
    float ir = gi[q], iz = gi[q + 1024], in_ = gi[q + 2048];
    float hr = gh[q], hz = gh[q + 1024], hn = gh[q + 2048];
    float r = 1.f / (1.f + __expf(-(ir + hr)));
    float z = 1.f / (1.f + __expf(-(iz + hz)));
    float n = tanhf(in_ + r * hn);
    float h = (1.f - z) * n + z * hprev[idx];
    out1[idx] = h;
    if (out2) out2[idx] = h;
}

// ---------------- launch ----------------
extern "C" void kernel_launch(void* const* d_in, const int* in_sizes, int n_in,
                              void* d_out, int out_size) {
    const int*   cur    = (const int*)d_in[0];
    const float* state  = (const float*)d_in[1];
    const float* enc    = (const float*)d_in[2];
    const float* emb    = (const float*)d_in[3];
    const float* w_att1 = (const float*)d_in[4];
    const float* w_att2 = (const float*)d_in[5];
    const float* w_ih0  = (const float*)d_in[6];
    const float* w_hh0  = (const float*)d_in[7];
    const float* b_ih0  = (const float*)d_in[8];
    const float* b_hh0  = (const float*)d_in[9];
    const float* w_ih1  = (const float*)d_in[10];
    const float* w_hh1  = (const float*)d_in[11];
    const float* b_ih1  = (const float*)d_in[12];
    const float* b_hh1  = (const float*)d_in[13];
    const float* w_out  = (const float*)d_in[14];
    const float* b_out  = (const float*)d_in[15];

    float* out = (float*)d_out;
    float* st0 = out + (size_t)BATCH * VOCAB;      // new_state layer 0
    float* st1 = st0 + BATCH * HID;                // new_state layer 1

    float *p_dproj, *p_x, *p_gi, *p_gh, *p_h0;
    cudaGetSymbolAddress((void**)&p_dproj, g_dproj);
    cudaGetSymbolAddress((void**)&p_x,     g_x);
    cudaGetSymbolAddress((void**)&p_gi,    g_gi);
    cudaGetSymbolAddress((void**)&p_gh,    g_gh);
    cudaGetSymbolAddress((void**)&p_h0,    g_h0);

    const float* dec = state + (size_t)BATCH * HID;          // state[-1] = layer 1

    // 1. dproj = dec @ w1_d   (w1_d = w_att1 rows [1024:2048], [K][N] layout)
    gemm64<false><<<16, 256>>>(dec, w_att1 + (size_t)HID * HID, nullptr,
                               p_dproj, HID, HID, HID);
    // 2. attention energies (fused GEMM + tanh + project)
    attn_kernel<<<dim3(16, 1024), 256>>>(enc, w_att1, w_att2);
    // 3. softmax over time
    softmax_kernel<<<BATCH, 256>>>();
    // 4. context vector
    context_kernel<<<dim3(BATCH, 8), 1024>>>(enc);
    // 5. x = concat(emb, c)
    build_x<<<BATCH, 512>>>(cur, emb);
    // 6. GRU layer 0
    gemm64<true><<<48, 256>>>(p_x,   w_ih0, b_ih0, p_gi, 3 * HID, EMBED + HID, 3 * HID);
    gemm64<true><<<48, 256>>>(state, w_hh0, b_hh0, p_gh, 3 * HID, HID,         3 * HID);
    gru_gates<<<256, 256>>>(state, st0, p_h0);
    // 7. GRU layer 1
    gemm64<true><<<48, 256>>>(p_h0, w_ih1, b_ih1, p_gi, 3 * HID, HID, 3 * HID);
    gemm64<true><<<48, 256>>>(dec,  w_hh1, b_hh1, p_gh, 3 * HID, HID, 3 * HID);
    gru_gates<<<256, 256>>>(dec, st1, nullptr);
    // 8. logits = h1 @ w_out^T + b_out
    gemm64<true><<<(VOCAB + 63) / 64, 256>>>(st1, w_out, b_out, out, VOCAB, HID, VOCAB);
}

// round 3
// speedup vs baseline: 2.0483x; 2.0483x over previous
#include <cuda_runtime.h>
#include <cuda_fp16.h>
#include <cstdint>
#include <cstddef>

#define HID    1024
#define EMBED  512
#define BATCH  64
#define MAXLEN 1024
#define VOCAB  50257
#define NCHUNK 8            // 1024 attn dims / 128 per block

// ---------------- scratch (no allocations allowed) ----------------
__device__ float  g_dproj[BATCH * HID];
__device__ float  g_epart[NCHUNK * MAXLEN * BATCH];
__device__ float  g_alpha[MAXLEN * BATCH];
__device__ float  g_cpart[8 * BATCH * HID];
__device__ float  g_x[BATCH * (EMBED + HID)];
__device__ float  g_gi[BATCH * 3 * HID];
__device__ float  g_gh[BATCH * 3 * HID];
__device__ float  g_h0[BATCH * HID];
__device__ __half g_bh[HID * HID];   // w1e^T fp16-hi   [n][k]
__device__ __half g_bl[HID * HID];   // w1e^T fp16-lo   [n][k]

// ---------------- prep: transpose + fp16-split w1e -> g_bh/g_bl [n][k] ----------------
__global__ void prep_b(const float* __restrict__ w1e) {
    __shared__ float tile[32][33];
    int k0 = blockIdx.x * 32, n0 = blockIdx.y * 32;
    int tx = threadIdx.x, ty = threadIdx.y;
    for (int i = ty; i < 32; i += 8)
        tile[i][tx] = w1e[(size_t)(k0 + i) * HID + n0 + tx];
    __syncthreads();
    for (int i = ty; i < 32; i += 8) {
        float v = tile[tx][i];                 // w1e[k0+tx][n0+i]
        __half hi = __float2half_rn(v);
        __half lo = __float2half_rn(v - __half2float(hi));
        g_bh[(size_t)(n0 + i) * HID + k0 + tx] = hi;
        g_bl[(size_t)(n0 + i) * HID + k0 + tx] = lo;
    }
}

// ---------------- mma.sync m16n8k16 fp16 -> fp32 ----------------
__device__ __forceinline__ void mma16816(float* d, const uint32_t* a, const uint32_t* b) {
    asm volatile("mma.sync.aligned.m16n8k16.row.col.f32.f16.f16.f32 "
                 "{%0,%1,%2,%3}, {%4,%5,%6,%7}, {%8,%9}, {%0,%1,%2,%3};"
                 : "+f"(d[0]), "+f"(d[1]), "+f"(d[2]), "+f"(d[3])
                 : "r"(a[0]), "r"(a[1]), "r"(a[2]), "r"(a[3]),
                   "r"(b[0]), "r"(b[1]));
}

// ---------------- attention GEMM (fp16x3 tensor core) + fused epilogue ----------------
// block: 128 rows (enc) x 128 cols (attn dim), K=1024 in 32-chunks, double buffered.
// smem stride 40 halves (80 B): conflict-free fragment loads (rows 0..7 map to
// disjoint bank quads: r*20 mod 32 = {0,20,8,28,16,4,24,12}).
#define ASTRIDE 40
#define STAGE_BYTES 20480            // (hi+lo) * 128*40*2B
#define SMEM_TOTAL_ATT 81920

__global__ void __launch_bounds__(256, 1)
attn_mma(const float* __restrict__ enc, const float* __restrict__ w2) {
    extern __shared__ char smem[];
    const int bn = blockIdx.x;       // 0..7   n-chunk (fast -> A-tile L2 reuse)
    const int mt = blockIdx.y;       // 0..511 row tile
    const int tid = threadIdx.x;
    const int wid = tid >> 5, lane = tid & 31;
    const int wm = wid >> 2, wn = wid & 3;     // warp grid 2(M) x 4(N)
    const int qr = lane >> 2, qc = lane & 3;

    const float*  Abase = enc + (size_t)mt * 128 * HID;
    const __half* Bh = g_bh + (size_t)(bn * 128) * HID;
    const __half* Bl = g_bl + (size_t)(bn * 128) * HID;

    float acc[4][4][4] = {};

    // prefetch registers
    float4 av[4];
    uint4  bvh[2], bvl[2];

    auto load_regs = [&](int kt) {
        #pragma unroll
        for (int i = 0; i < 4; i++) {
            int idx = tid + i * 256;          // 1024 float4s: A tile 128x32 fp32
            int r = idx >> 3, c4 = idx & 7;
            av[i] = *(const float4*)(Abase + (size_t)r * HID + kt * 32 + c4 * 4);
        }
        #pragma unroll
        for (int i = 0; i < 2; i++) {
            int idx = tid + i * 256;          // 512 uint4s: B tile 128x32 fp16
            int n = idx >> 2, kc = idx & 3;
            bvh[i] = *(const uint4*)(Bh + (size_t)n * HID + kt * 32 + kc * 8);
            bvl[i] = *(const uint4*)(Bl + (size_t)n * HID + kt * 32 + kc * 8);
        }
    };
    auto store_smem = [&](int s) {
        __half* sAh = (__half*)(smem + s * STAGE_BYTES);
        __half* sAl = sAh + 128 * ASTRIDE;
        __half* sBh = (__half*)(smem + 40960 + s * STAGE_BYTES);
        __half* sBl = sBh + 128 * ASTRIDE;
        #pragma unroll
        for (int i = 0; i < 4; i++) {
            int idx = tid + i * 256;
            int r = idx >> 3, c4 = idx & 7;
            float x[4] = {av[i].x, av[i].y, av[i].z, av[i].w};
            __half h[4], l[4];
            #pragma unroll
            for (int e = 0; e < 4; e++) {
                h[e] = __float2half_rn(x[e]);
                l[e] = __float2half_rn(x[e] - __half2float(h[e]));
            }
            *(uint2*)(sAh + r * ASTRIDE + c4 * 4) = *(uint2*)h;
            *(uint2*)(sAl + r * ASTRIDE + c4 * 4) = *(uint2*)l;
        }
        #pragma unroll
        for (int i = 0; i < 2; i++) {
            int idx = tid + i * 256;
            int n = idx >> 2, kc = idx & 3;
            *(uint4*)(sBh + n * ASTRIDE + kc * 8) = bvh[i];
            *(uint4*)(sBl + n * ASTRIDE + kc * 8) = bvl[i];
        }
    };
    auto compute = [&](int s) {
        const __half* sAh = (const __half*)(smem + s * STAGE_BYTES);
        const __half* sAl = sAh + 128 * ASTRIDE;
        const __half* sBh = (const __half*)(smem + 40960 + s * STAGE_BYTES);
        const __half* sBl = sBh + 128 * ASTRIDE;
        #pragma unroll
        for (int ks = 0; ks < 32; ks += 16) {
            const int c0 = ks + qc * 2;
            uint32_t ah[4][4], al[4][4], bh[4][2], bl[4][2];
            #pragma unroll
            for (int m = 0; m < 4; m++) {
                const __half* p0 = sAh + (wm * 64 + m * 16 + qr) * ASTRIDE;
                const __half* p1 = sAl + (wm * 64 + m * 16 + qr) * ASTRIDE;
                ah[m][0] = *(const uint32_t*)(p0 + c0);
                ah[m][1] = *(const uint32_t*)(p0 + 8 * ASTRIDE + c0);
                ah[m][2] = *(const uint32_t*)(p0 + c0 + 8);
                ah[m][3] = *(const uint32_t*)(p0 + 8 * ASTRIDE + c0 + 8);
                al[m][0] = *(const uint32_t*)(p1 + c0);
                al[m][1] = *(const uint32_t*)(p1 + 8 * ASTRIDE + c0);
                al[m][2] = *(const uint32_t*)(p1 + c0 + 8);
                al[m][3] = *(const uint32_t*)(p1 + 8 * ASTRIDE + c0 + 8);
            }
            #pragma unroll
            for (int n = 0; n < 4; n++) {
                const __half* p0 = sBh + (wn * 32 + n * 8 + qr) * ASTRIDE;
                const __half* p1 = sBl + (wn * 32 + n * 8 + qr) * ASTRIDE;
                bh[n][0] = *(const uint32_t*)(p0 + c0);
                bh[n][1] = *(const uint32_t*)(p0 + c0 + 8);
                bl[n][0] = *(const uint32_t*)(p1 + c0);
                bl[n][1] = *(const uint32_t*)(p1 + c0 + 8);
            }
            #pragma unroll
            for (int m = 0; m < 4; m++)
                #pragma unroll
                for (int n = 0; n < 4; n++) mma16816(acc[m][n], ah[m], bh[n]);
            #pragma unroll
            for (int m = 0; m < 4; m++)
                #pragma unroll
                for (int n = 0; n < 4; n++) mma16816(acc[m][n], al[m], bh[n]);
            #pragma unroll
            for (int m = 0; m < 4; m++)
                #pragma unroll
                for (int n = 0; n < 4; n++) mma16816(acc[m][n], ah[m], bl[n]);
        }
    };

    load_regs(0);
    store_smem(0);
    __syncthreads();
    for (int kt = 0; kt < 32; kt++) {
        if (kt < 31) load_regs(kt + 1);
        compute(kt & 1);
        if (kt < 31) {
            __syncthreads();
            store_smem((kt + 1) & 1);
            __syncthreads();
        }
    }

    // ---- epilogue: e_partial[row] = sum_n tanh(acc + dproj[b][n]) * w2[n] ----
    float rsum[4][2] = {};
    #pragma unroll
    for (int m = 0; m < 4; m++) {
        #pragma unroll
        for (int n = 0; n < 4; n++) {
            int ng0 = bn * 128 + wn * 32 + n * 8 + qc * 2;
            float w20 = w2[ng0], w21 = w2[ng0 + 1];
            #pragma unroll
            for (int pr = 0; pr < 2; pr++) {
                int row_local = wm * 64 + m * 16 + qr + pr * 8;
                int b = row_local & 63;
                const float* dp = g_dproj + (size_t)b * HID + ng0;
                rsum[m][pr] += tanhf(acc[m][n][pr * 2 + 0] + dp[0]) * w20
                             + tanhf(acc[m][n][pr * 2 + 1] + dp[1]) * w21;
            }
        }
    }
    #pragma unroll
    for (int m = 0; m < 4; m++)
        #pragma unroll
        for (int pr = 0; pr < 2; pr++) {
            float v = rsum[m][pr];
            v += __shfl_xor_sync(0xffffffffu, v, 1);
            v += __shfl_xor_sync(0xffffffffu, v, 2);
            rsum[m][pr] = v;
        }
    float* part = (float*)smem;           // [128][4], reuses stage-0 A (safe post-compute)
    __syncthreads();
    if (qc == 0) {
        #pragma unroll
        for (int m = 0; m < 4; m++)
            #pragma unroll
            for (int pr = 0; pr < 2; pr++)
                part[(wm * 64 + m * 16 + qr + pr * 8) * 4 + wn] = rsum[m][pr];
    }
    __syncthreads();
    if (tid < 128) {
        float e = part[tid * 4 + 0] + part[tid * 4 + 1] + part[tid * 4 + 2] + part[tid * 4 + 3];
        g_epart[(size_t)bn * (MAXLEN * BATCH) + mt * 128 + tid] = e;
    }
}

// ---------------- generic M=64 GEMM ----------------
template <bool BT>
__global__ void gemm64(const float* __restrict__ A, const float* __restrict__ B,
                       const float* __restrict__ bias, float* __restrict__ C,
                       int N, int K, int ldc) {
    __shared__ float As[64][16];
    __shared__ float Bs[16][64];
    const int nT  = blockIdx.x * 64;
    const int tid = threadIdx.x;
    const int tx  = tid & 15, ty = tid >> 4;
    const int m4  = tid >> 2, kq = tid & 3;

    float acc[4][4] = {};
    for (int k0 = 0; k0 < K; k0 += 16) {
        float4 avv = *(const float4*)(A + (size_t)m4 * K + k0 + kq * 4);
        *(float4*)&As[m4][kq * 4] = avv;
        if (BT) {
            int n = tid >> 2;
            int gn = nT + n;
            float4 bv = make_float4(0.f, 0.f, 0.f, 0.f);
            if (gn < N) bv = *(const float4*)(B + (size_t)gn * K + k0 + kq * 4);
            Bs[kq * 4 + 0][n] = bv.x;
            Bs[kq * 4 + 1][n] = bv.y;
            Bs[kq * 4 + 2][n] = bv.z;
            Bs[kq * 4 + 3][n] = bv.w;
        } else {
            #pragma unroll
            for (int e2 = 0; e2 < 4; e2++) {
                int lin = tid + e2 * 256;
                int kk = lin >> 6, n = lin & 63;
                int gn = nT + n;
                Bs[kk][n] = (gn < N) ? B[(size_t)(k0 + kk) * N + gn] : 0.f;
            }
        }
        __syncthreads();
        #pragma unroll
        for (int kk = 0; kk < 16; kk++) {
            float4 b4 = *(const float4*)&Bs[kk][tx * 4];
            float bj[4] = {b4.x, b4.y, b4.z, b4.w};
            #pragma unroll
            for (int i = 0; i < 4; i++) {
                float a = As[ty * 4 + i][kk];
                #pragma unroll
                for (int j = 0; j < 4; j++) acc[i][j] = fmaf(a, bj[j], acc[i][j]);
            }
        }
        __syncthreads();
    }
    #pragma unroll
    for (int i = 0; i < 4; i++) {
        int m = ty * 4 + i;
        #pragma unroll
        for (int j = 0; j < 4; j++) {
            int n = nT + tx * 4 + j;
            if (n < N) {
                float v = acc[i][j];
                if (bias) v += bias[n];
                C[(size_t)m * ldc + n] = v;
            }
        }
    }
}

// ---------------- softmax over t (8 partials) ----------------
__global__ void softmax_kernel() {
    const int b = blockIdx.x;
    __shared__ float es[MAXLEN];
    __shared__ float red[256];
    const int tid = threadIdx.x;

    float mx = -1e30f;
    for (int t = tid; t < MAXLEN; t += 256) {
        float s = 0.f;
        #pragma unroll
        for (int p = 0; p < NCHUNK; p++) s += g_epart[p * (MAXLEN * BATCH) + t * 64 + b];
        es[t] = s;
        mx = fmaxf(mx, s);
    }
    red[tid] = mx; __syncthreads();
    for (int s2 = 128; s2; s2 >>= 1) {
        if (tid < s2) red[tid] = fmaxf(red[tid], red[tid + s2]);
        __syncthreads();
    }
    mx = red[0]; __syncthreads();

    float sum = 0.f;
    for (int t = tid; t < MAXLEN; t += 256) {
        float v = __expf(es[t] - mx);
        es[t] = v;
        sum += v;
    }
    red[tid] = sum; __syncthreads();
    for (int s2 = 128; s2; s2 >>= 1) {
        if (tid < s2) red[tid] += red[tid + s2];
        __syncthreads();
    }
    float inv = 1.f / red[0];
    for (int t = tid; t < MAXLEN; t += 256) g_alpha[t * 64 + b] = es[t] * inv;
}

// ---------------- context ----------------
__global__ void context_kernel(const float* __restrict__ E) {
    const int b = blockIdx.x, seg = blockIdx.y;
    const int h = threadIdx.x;
    float acc = 0.f;
    #pragma unroll 4
    for (int t = seg * 128; t < (seg + 1) * 128; t++)
        acc = fmaf(g_alpha[t * 64 + b], E[((size_t)t * 64 + b) * HID + h], acc);
    g_cpart[(seg * BATCH + b) * HID + h] = acc;
}

// ---------------- x = concat(embedding[cur], c) ----------------
__global__ void build_x(const int* __restrict__ cur, const float* __restrict__ emb) {
    const int b = blockIdx.x, tid = threadIdx.x;
    const int tok = cur[b];
    for (int k = tid; k < EMBED; k += 512)
        g_x[b * (EMBED + HID) + k] = emb[(size_t)tok * EMBED + k];
    for (int k = tid; k < HID; k += 512) {
        float s = 0.f;
        #pragma unroll
        for (int p = 0; p < 8; p++) s += g_cpart[(p * BATCH + b) * HID + k];
        g_x[b * (EMBED + HID) + EMBED + k] = s;
    }
}

// ---------------- GRU gates ----------------
__global__ void gru_gates(const float* __restrict__ hprev,
                          float* __restrict__ out1, float* __restrict__ out2) {
    const int idx = blockIdx.x * 256 + threadIdx.x;
    const int b = idx >> 10, q = idx & 1023;
    const float* gi = g_gi + b * 3072;
    const float* gh = g_gh + b * 3072;
    float ir = gi[q], iz = gi[q + 1024], in_ = gi[q + 2048];
    float hr = gh[q], hz = gh[q + 1024], hn = gh[q + 2048];
    float r = 1.f / (1.f + __expf(-(ir + hr)));
    float z = 1.f / (1.f + __expf(-(iz + hz)));
    float n = tanhf(in_ + r * hn);
    float h = (1.f - z) * n + z * hprev[idx];
    out1[idx] = h;
    if (out2) out2[idx] = h;
}

// ---------------- launch ----------------
extern "C" void kernel_launch(void* const* d_in, const int* in_sizes, int n_in,
                              void* d_out, int out_size) {
    const int*   cur    = (const int*)d_in[0];
    const float* state  = (const float*)d_in[1];
    const float* enc    = (const float*)d_in[2];
    const float* emb    = (const float*)d_in[3];
    const float* w_att1 = (const float*)d_in[4];
    const float* w_att2 = (const float*)d_in[5];
    const float* w_ih0  = (const float*)d_in[6];
    const float* w_hh0  = (const float*)d_in[7];
    const float* b_ih0  = (const float*)d_in[8];
    const float* b_hh0  = (const float*)d_in[9];
    const float* w_ih1  = (const float*)d_in[10];
    const float* w_hh1  = (const float*)d_in[11];
    const float* b_ih1  = (const float*)d_in[12];
    const float* b_hh1  = (const float*)d_in[13];
    const float* w_out  = (const float*)d_in[14];
    const float* b_out  = (const float*)d_in[15];

    float* out = (float*)d_out;
    float* st0 = out + (size_t)BATCH * VOCAB;
    float* st1 = st0 + BATCH * HID;

    float *p_dproj, *p_x, *p_gi, *p_gh, *p_h0;
    cudaGetSymbolAddress((void**)&p_dproj, g_dproj);
    cudaGetSymbolAddress((void**)&p_x,     g_x);
    cudaGetSymbolAddress((void**)&p_gi,    g_gi);
    cudaGetSymbolAddress((void**)&p_gh,    g_gh);
    cudaGetSymbolAddress((void**)&p_h0,    g_h0);

    cudaFuncSetAttribute(attn_mma, cudaFuncAttributeMaxDynamicSharedMemorySize,
                         SMEM_TOTAL_ATT);

    const float* dec = state + (size_t)BATCH * HID;

    // 0. prep: w1e -> transposed fp16 hi/lo
    prep_b<<<dim3(32, 32), dim3(32, 8)>>>(w_att1);
    // 1. dproj = dec @ w1_d
    gemm64<false><<<16, 256>>>(dec, w_att1 + (size_t)HID * HID, nullptr,
                               p_dproj, HID, HID, HID);
    // 2. attention energies: fp16x3 tensor-core GEMM + fused tanh/project
    attn_mma<<<dim3(NCHUNK, 512), 256, SMEM_TOTAL_ATT>>>(enc, w_att2);
    // 3. softmax over time
    softmax_kernel<<<BATCH, 256>>>();
    // 4. context vector
    context_kernel<<<dim3(BATCH, 8), 1024>>>(enc);
    // 5. x = concat(emb, c)
    build_x<<<BATCH, 512>>>(cur, emb);
    // 6. GRU layer 0
    gemm64<true><<<48, 256>>>(p_x,   w_ih0, b_ih0, p_gi, 3 * HID, EMBED + HID, 3 * HID);
    gemm64<true><<<48, 256>>>(state, w_hh0, b_hh0, p_gh, 3 * HID, HID,         3 * HID);
    gru_gates<<<256, 256>>>(state, st0, p_h0);
    // 7. GRU layer 1
    gemm64<true><<<48, 256>>>(p_h0, w_ih1, b_ih1, p_gi, 3 * HID, HID, 3 * HID);
    gemm64<true><<<48, 256>>>(dec,  w_hh1, b_hh1, p_gh, 3 * HID, HID, 3 * HID);
    gru_gates<<<256, 256>>>(dec, st1, nullptr);
    // 8. logits
    gemm64<true><<<(VOCAB + 63) / 64, 256>>>(st1, w_out, b_out, out, VOCAB, HID, VOCAB);
}